// round 8
// baseline (speedup 1.0000x reference)
#include <cuda_runtime.h>
#include <cstdint>

// Shapes fixed by the problem: x (64,64,128,128) fp32, coeff (64,32) fp32, out (64,64) fp32.
#define N_ELEM   67108864   // 64*64*128*128
#define N_F4     16777216   // N_ELEM/4
#define N_PLANES 4096       // N*C
#define HW4      4096       // 128*128/4
#define BINS     32
#define GRID     592        // 148 SMs * 4 blocks co-resident with wide resource margin
#define SEVENERS 544        // 4096 = 592*6 + 544: planes p=b+592k, k=6 exists iff b<544
#define MARGIN   0.001f     // bin-fraction safety margin (true error < ~3e-5)

__device__ float2   g_partials[GRID];
__device__ unsigned g_cnt[2];   // [0]=phase barrier, [1]=exit ticket; last arriver resets both

__global__ void __launch_bounds__(256, 4)
hpool_fused(const float4* __restrict__ x, const float* __restrict__ coeff,
            float* __restrict__ out) {
    __shared__ float s_red[8];
    __shared__ float s_mm[2];

    const int b  = blockIdx.x;
    const int t  = threadIdx.x;
    const int np = (b < SEVENERS) ? 7 : 6;

    // ================= phase 1: min/max over this block's planes (forward) ==========
    float lo =  3.402823466e38f;
    float hi = -3.402823466e38f;
    for (int k = 0; k < np; k++) {
        const float4* __restrict__ p = x + (size_t)(b + GRID * k) * HW4;
        #pragma unroll 4
        for (int it = 0; it < 16; it++) {
            float4 v = p[it * 256 + t];
            lo = fminf(lo, fminf(fminf(v.x, v.y), fminf(v.z, v.w)));
            hi = fmaxf(hi, fmaxf(fmaxf(v.x, v.y), fmaxf(v.z, v.w)));
        }
    }
    #pragma unroll
    for (int o = 16; o; o >>= 1) {
        lo = fminf(lo, __shfl_xor_sync(0xFFFFFFFFu, lo, o));
        hi = fmaxf(hi, __shfl_xor_sync(0xFFFFFFFFu, hi, o));
    }
    if ((t & 31) == 0) s_red[t >> 5] = lo;
    __syncthreads();
    if (t < 32) {
        float a = (t < 8) ? s_red[t] : 3.402823466e38f;
        #pragma unroll
        for (int o = 4; o; o >>= 1) a = fminf(a, __shfl_xor_sync(0xFFFFFFFFu, a, o));
        if (t == 0) s_mm[0] = a;
    }
    __syncthreads();
    if ((t & 31) == 0) s_red[t >> 5] = hi;
    __syncthreads();
    if (t < 32) {
        float a = (t < 8) ? s_red[t] : -3.402823466e38f;
        #pragma unroll
        for (int o = 4; o; o >>= 1) a = fmaxf(a, __shfl_xor_sync(0xFFFFFFFFu, a, o));
        if (t == 0) s_mm[1] = a;
    }
    __syncthreads();

    // ===== grid barrier (all 592 blocks co-resident: 4/SM by resource arithmetic) ===
    if (t == 0) {
        g_partials[b] = make_float2(s_mm[0], s_mm[1]);
        __threadfence();                       // release partial before arriving
        atomicAdd(&g_cnt[0], 1u);
        while (*(volatile unsigned*)&g_cnt[0] < (unsigned)GRID) __nanosleep(128);
    }
    __syncthreads();
    __threadfence();                           // acquire all partials

    // ================= reduce partials -> global min/max =============================
    {
        float plo =  3.402823466e38f;
        float phi = -3.402823466e38f;
        for (int i = t; i < GRID; i += 256) {
            float2 pp = g_partials[i];
            plo = fminf(plo, pp.x);
            phi = fmaxf(phi, pp.y);
        }
        #pragma unroll
        for (int o = 16; o; o >>= 1) {
            plo = fminf(plo, __shfl_xor_sync(0xFFFFFFFFu, plo, o));
            phi = fmaxf(phi, __shfl_xor_sync(0xFFFFFFFFu, phi, o));
        }
        __syncthreads();
        if ((t & 31) == 0) s_red[t >> 5] = plo;
        __syncthreads();
        if (t < 32) {
            float a = (t < 8) ? s_red[t] : 3.402823466e38f;
            #pragma unroll
            for (int o = 4; o; o >>= 1) a = fminf(a, __shfl_xor_sync(0xFFFFFFFFu, a, o));
            if (t == 0) s_mm[0] = a;
        }
        __syncthreads();
        if ((t & 31) == 0) s_red[t >> 5] = phi;
        __syncthreads();
        if (t < 32) {
            float a = (t < 8) ? s_red[t] : -3.402823466e38f;
            #pragma unroll
            for (int o = 4; o; o >>= 1) a = fmaxf(a, __shfl_xor_sync(0xFFFFFFFFu, a, o));
            if (t == 0) s_mm[1] = a;
        }
        __syncthreads();
    }

    const float xmin = s_mm[0];
    const float xmax = s_mm[1];
    // jnp.linspace fp32 semantics: delta=(stop-start)/32; tau[i]=rn(start + rn(i*delta))
    const float delta     = __fdiv_rn(__fsub_rn(xmax, xmin), 32.0f);
    const float inv_delta = __frcp_rn(delta);
    const float nbase     = -xmin * inv_delta;

    // ====== phase 2: same planes, REVERSE order (harvest this SM's L1/L2 residue) ===
    for (int k = np - 1; k >= 0; k--) {
        const int plane = b + GRID * k;
        const int c = plane & 63;
        const float cf_lane = coeff[c * BINS + (t & 31)];
        const float4* __restrict__ p = x + (size_t)plane * HW4;
        float acc = 0.0f;

        #pragma unroll 4
        for (int it = 15; it >= 0; it--) {     // back-to-front: hottest lines first
            float4 v = p[it * 256 + t];
            float vv[4] = {v.x, v.y, v.z, v.w};
            #pragma unroll
            for (int j = 0; j < 4; j++) {
                const float xv = vv[j];
                // approximate bin index; exact unless within MARGIN of a boundary.
                const float f = fmaf(xv, inv_delta, nbase);
                int i0 = (int)f;               // trunc clamps tiny negatives to 0
                const float r = rintf(f);
                if (fabsf(f - r) < MARGIN) {   // rare: exact linspace fix-up (handles clamps)
                    const int ir = (int)r;
                    const float tau_r = __fadd_rn(xmin, __fmul_rn((float)ir, delta));
                    i0 = (xv >= tau_r) ? ir : ir - 1;
                    i0 = min(max(i0, 0), BINS - 1);
                }
                float th;
                asm("tanh.approx.f32 %0, %1;" : "=f"(th) : "f"(xv));
                const float cf = __shfl_sync(0xFFFFFFFFu, cf_lane, i0);
                acc = fmaf(th, cf, acc);
            }
        }

        // block reduce (8 warps)
        #pragma unroll
        for (int o = 16; o; o >>= 1) acc += __shfl_xor_sync(0xFFFFFFFFu, acc, o);
        __syncthreads();
        if ((t & 31) == 0) s_red[t >> 5] = acc;
        __syncthreads();
        if (t < 32) {
            float a = (t < 8) ? s_red[t] : 0.0f;
            #pragma unroll
            for (int o = 4; o; o >>= 1) a += __shfl_xor_sync(0xFFFFFFFFu, a, o);
            if (t == 0) out[plane] = a;
        }
        __syncthreads();
    }

    // ================= exit ticket: last block resets both counters ==================
    if (t == 0) {
        unsigned o = atomicAdd(&g_cnt[1], 1u);
        if (o == (unsigned)(GRID - 1)) {
            g_cnt[0] = 0u;
            g_cnt[1] = 0u;
            __threadfence();
        }
    }
}

extern "C" void kernel_launch(void* const* d_in, const int* in_sizes, int n_in,
                              void* d_out, int out_size) {
    const float4* x     = (const float4*)d_in[0];
    const float*  coeff = (const float*)d_in[1];
    float*        out   = (float*)d_out;

    hpool_fused<<<GRID, 256>>>(x, coeff, out);
}

// round 12
// speedup vs baseline: 1.1481x; 1.1481x over previous
#include <cuda_runtime.h>
#include <cstdint>

// Shapes fixed by the problem: x (64,64,128,128) fp32, coeff (64,32) fp32, out (64,64) fp32.
#define N_ELEM   67108864   // 64*64*128*128
#define N_F4     16777216   // N_ELEM/4
#define N_PLANES 4096       // N*C
#define HW4      4096       // 128*128/4
#define BINS     32
#define MM_GRID  1184       // 148 SMs * 8 blocks: exactly one full wave
#define MARGIN   2.0e-4f    // bin-fraction safety margin (true error < ~3e-5)

// per-block min/max partials (written fresh every launch -> no init kernel, no atomics)
__device__ float2 g_partials[MM_GRID];

__global__ void __launch_bounds__(256) minmax_kernel(const float4* __restrict__ x) {
    float lo =  3.402823466e38f;
    float hi = -3.402823466e38f;
    const int base   = blockIdx.x * 256 + threadIdx.x;
    const int stride = MM_GRID * 256;
    #pragma unroll 8
    for (int i = base; i < N_F4; i += stride) {
        float4 v = x[i];
        lo = fminf(lo, fminf(fminf(v.x, v.y), fminf(v.z, v.w)));
        hi = fmaxf(hi, fmaxf(fmaxf(v.x, v.y), fmaxf(v.z, v.w)));
    }
    #pragma unroll
    for (int o = 16; o; o >>= 1) {
        lo = fminf(lo, __shfl_xor_sync(0xFFFFFFFFu, lo, o));
        hi = fmaxf(hi, __shfl_xor_sync(0xFFFFFFFFu, hi, o));
    }
    __shared__ float s_lo[8], s_hi[8];
    const int t = threadIdx.x;
    if ((t & 31) == 0) { s_lo[t >> 5] = lo; s_hi[t >> 5] = hi; }
    __syncthreads();
    if (t < 32) {
        lo = (t < 8) ? s_lo[t] :  3.402823466e38f;
        hi = (t < 8) ? s_hi[t] : -3.402823466e38f;
        #pragma unroll
        for (int o = 4; o; o >>= 1) {
            lo = fminf(lo, __shfl_xor_sync(0xFFFFFFFFu, lo, o));
            hi = fmaxf(hi, __shfl_xor_sync(0xFFFFFFFFu, hi, o));
        }
        if (t == 0) g_partials[blockIdx.x] = make_float2(lo, hi);
    }
}

__global__ void __launch_bounds__(256) hpool_kernel(const float4* __restrict__ x,
                                                    const float* __restrict__ coeff,
                                                    float* __restrict__ out) {
    __shared__ float s_red[8];
    __shared__ float s_mm[2];

    const int t = threadIdx.x;

    // ---- prologue: reduce per-block minmax partials (deterministic, L2-resident) ----
    {
        float lo =  3.402823466e38f;
        float hi = -3.402823466e38f;
        #pragma unroll
        for (int i = t; i < MM_GRID; i += 256) {
            float2 p = g_partials[i];
            lo = fminf(lo, p.x);
            hi = fmaxf(hi, p.y);
        }
        #pragma unroll
        for (int o = 16; o; o >>= 1) {
            lo = fminf(lo, __shfl_xor_sync(0xFFFFFFFFu, lo, o));
            hi = fmaxf(hi, __shfl_xor_sync(0xFFFFFFFFu, hi, o));
        }
        if ((t & 31) == 0) { s_red[(t >> 5)] = lo; }
        __syncthreads();
        if (t < 32) {
            float a = (t < 8) ? s_red[t] : 3.402823466e38f;
            #pragma unroll
            for (int o = 4; o; o >>= 1) a = fminf(a, __shfl_xor_sync(0xFFFFFFFFu, a, o));
            if (t == 0) s_mm[0] = a;
        }
        __syncthreads();
        if ((t & 31) == 0) { s_red[(t >> 5)] = hi; }
        __syncthreads();
        if (t < 32) {
            float a = (t < 8) ? s_red[t] : -3.402823466e38f;
            #pragma unroll
            for (int o = 4; o; o >>= 1) a = fmaxf(a, __shfl_xor_sync(0xFFFFFFFFu, a, o));
            if (t == 0) s_mm[1] = a;
        }
        __syncthreads();
    }

    const float xmin = s_mm[0];
    const float xmax = s_mm[1];
    // jnp.linspace fp32 semantics: delta=(stop-start)/32; tau[i]=rn(start + rn(i*delta))
    const float delta     = __fdiv_rn(__fsub_rn(xmax, xmin), 32.0f);
    const float inv_delta = __frcp_rn(delta);
    const float nbase     = -xmin * inv_delta;

    // Reverse plane order: minmax streamed forward, its tail is L2-resident
    // (and this leaves the FRONT of x in L2 for the next graph replay's minmax).
    const int plane = (N_PLANES - 1) - (int)blockIdx.x;
    const int c = plane & 63;

    // lane l holds coeff[c][l]; gather via shfl (BINS == warp size)
    const float cf_lane = coeff[c * BINS + (t & 31)];

    const float4* __restrict__ p = x + (size_t)plane * HW4;
    float acc0 = 0.0f, acc1 = 0.0f;

    #pragma unroll 4
    for (int it = 0; it < 16; it++) {
        float4 v = p[it * 256 + t];
        float vv[4] = {v.x, v.y, v.z, v.w};
        #pragma unroll
        for (int j = 0; j < 4; j++) {
            const float xv = vv[j];
            // approximate bin index; exact unless within MARGIN of a boundary.
            // No clamp needed: out-of-range f occurs only inside the MARGIN window,
            // where the fixup path clamps.
            const float f = fmaf(xv, inv_delta, nbase);
            int i0 = (int)f;                   // trunc clamps tiny negatives to 0
            const float r = rintf(f);
            if (fabsf(f - r) < MARGIN) {       // rare (~1.2% of warps): exact linspace fix-up
                const int ir = (int)r;
                const float tau_r = __fadd_rn(xmin, __fmul_rn((float)ir, delta));
                i0 = (xv >= tau_r) ? ir : ir - 1;
                i0 = min(max(i0, 0), BINS - 1);
            }
            float th;
            asm("tanh.approx.f32 %0, %1;" : "=f"(th) : "f"(xv));
            const float cf = __shfl_sync(0xFFFFFFFFu, cf_lane, i0);
            if (j & 1) acc1 = fmaf(th, cf, acc1);
            else       acc0 = fmaf(th, cf, acc0);
        }
    }
    float acc = acc0 + acc1;

    // block reduce (8 warps)
    #pragma unroll
    for (int o = 16; o; o >>= 1) acc += __shfl_xor_sync(0xFFFFFFFFu, acc, o);
    __syncthreads();  // s_red reuse
    if ((t & 31) == 0) s_red[t >> 5] = acc;
    __syncthreads();
    if (t < 32) {
        float a = (t < 8) ? s_red[t] : 0.0f;
        #pragma unroll
        for (int o = 4; o; o >>= 1) a += __shfl_xor_sync(0xFFFFFFFFu, a, o);
        if (t == 0) out[plane] = a;
    }
}

extern "C" void kernel_launch(void* const* d_in, const int* in_sizes, int n_in,
                              void* d_out, int out_size) {
    const float4* x     = (const float4*)d_in[0];
    const float*  coeff = (const float*)d_in[1];
    float*        out   = (float*)d_out;

    minmax_kernel<<<MM_GRID, 256>>>(x);
    hpool_kernel<<<N_PLANES, 256>>>(x, coeff, out);
}